// round 1
// baseline (speedup 1.0000x reference)
#include <cuda_runtime.h>

#define BATCH_ 8
#define H_ 64
#define W_ 64
#define L_ 4096          // H_*W_
#define DM_ 192          // d_model
#define E_ 384           // expanded inner dim
#define N_ 16            // d_state
#define R_ 12            // dt_rank
#define XD_ 44           // R_ + 2*N_
#define ROWS_ (BATCH_*L_) // 32768

// ---------------- scratch (device globals; no runtime allocation) -----------
__device__ float g_xz   [(size_t)ROWS_ * 2 * E_]; // in-proj output: [xs | z]
__device__ float g_u    [(size_t)ROWS_ * E_];     // conv+silu output
__device__ float g_xdbl [(size_t)ROWS_ * XD_];    // [dt_r | B | C]
__device__ float g_delta[(size_t)ROWS_ * E_];
__device__ float g_y    [(size_t)ROWS_ * E_];     // scan out + u*Dp
__device__ float g_g    [(size_t)ROWS_ * E_];     // gated (batch-summed) input to out-proj

// ---------------- generic SGEMM: C[M,N] = A[M,K] * B[N,K]^T ------------------
// 128x128x8 tile, 8x8 per thread, 256 threads. mode 1: softplus(acc + 2*bias[col]).
__global__ __launch_bounds__(256) void sgemm_nt(
    const float* __restrict__ A, int lda,
    const float* __restrict__ Bm, int ldb,
    float* __restrict__ C, int ldc,
    int M, int N, int K, int mode, const float* __restrict__ bias)
{
    __shared__ float As[8][128];
    __shared__ float Bs[8][128];
    const int tid  = threadIdx.x;
    const int row0 = blockIdx.y * 128;
    const int col0 = blockIdx.x * 128;
    const int aRow = tid >> 1;           // 0..127
    const int aCol = (tid & 1) << 2;     // 0 or 4
    const int tx   = tid & 15;
    const int ty   = tid >> 4;

    float acc[8][8];
    #pragma unroll
    for (int i = 0; i < 8; i++)
        #pragma unroll
        for (int j = 0; j < 8; j++) acc[i][j] = 0.f;

    for (int k0 = 0; k0 < K; k0 += 8) {
        float4 av = make_float4(0.f, 0.f, 0.f, 0.f);
        {
            int gr = row0 + aRow;
            if (gr < M) {
                const float* ap = A + (size_t)gr * lda + k0 + aCol;
                if (k0 + aCol + 3 < K) {
                    av = *reinterpret_cast<const float4*>(ap);
                } else {
                    float t0 = (k0 + aCol + 0 < K) ? ap[0] : 0.f;
                    float t1 = (k0 + aCol + 1 < K) ? ap[1] : 0.f;
                    float t2 = (k0 + aCol + 2 < K) ? ap[2] : 0.f;
                    float t3 = (k0 + aCol + 3 < K) ? ap[3] : 0.f;
                    av = make_float4(t0, t1, t2, t3);
                }
            }
        }
        float4 bv = make_float4(0.f, 0.f, 0.f, 0.f);
        {
            int gn = col0 + aRow;
            if (gn < N) {
                const float* bp = Bm + (size_t)gn * ldb + k0 + aCol;
                if (k0 + aCol + 3 < K) {
                    bv = *reinterpret_cast<const float4*>(bp);
                } else {
                    float t0 = (k0 + aCol + 0 < K) ? bp[0] : 0.f;
                    float t1 = (k0 + aCol + 1 < K) ? bp[1] : 0.f;
                    float t2 = (k0 + aCol + 2 < K) ? bp[2] : 0.f;
                    float t3 = (k0 + aCol + 3 < K) ? bp[3] : 0.f;
                    bv = make_float4(t0, t1, t2, t3);
                }
            }
        }
        As[aCol + 0][aRow] = av.x; As[aCol + 1][aRow] = av.y;
        As[aCol + 2][aRow] = av.z; As[aCol + 3][aRow] = av.w;
        Bs[aCol + 0][aRow] = bv.x; Bs[aCol + 1][aRow] = bv.y;
        Bs[aCol + 2][aRow] = bv.z; Bs[aCol + 3][aRow] = bv.w;
        __syncthreads();

        #pragma unroll
        for (int kk = 0; kk < 8; kk++) {
            float ra[8], rb[8];
            #pragma unroll
            for (int i = 0; i < 8; i++) ra[i] = As[kk][ty * 8 + i];
            #pragma unroll
            for (int j = 0; j < 8; j++) rb[j] = Bs[kk][tx * 8 + j];
            #pragma unroll
            for (int i = 0; i < 8; i++)
                #pragma unroll
                for (int j = 0; j < 8; j++)
                    acc[i][j] = fmaf(ra[i], rb[j], acc[i][j]);
        }
        __syncthreads();
    }

    #pragma unroll
    for (int i = 0; i < 8; i++) {
        int row = row0 + ty * 8 + i;
        if (row >= M) continue;
        #pragma unroll
        for (int j = 0; j < 8; j++) {
            int col = col0 + tx * 8 + j;
            if (col >= N) continue;
            float v = acc[i][j];
            if (mode == 1) {
                v += 2.f * bias[col];
                v = (v > 20.f) ? v : log1pf(__expf(v));   // softplus
            }
            C[(size_t)row * ldc + col] = v;
        }
    }
}

// ---------------- depthwise 7x7 conv + bias + SiLU, channel-last -------------
// input: xs = g_xz rows (stride 2*E_), first E_ entries. output: g_u (stride E_).
__global__ __launch_bounds__(128) void dwconv_silu(
    const float* __restrict__ xz, const float* __restrict__ cw,
    const float* __restrict__ cb, float* __restrict__ u)
{
    const int ec0 = blockIdx.x * 128;          // channel chunk
    const int e   = ec0 + threadIdx.x;
    const int ty0 = (blockIdx.y / (W_ / 8)) * 8;
    const int tx0 = (blockIdx.y % (W_ / 8)) * 8;
    const int b   = blockIdx.z;

    __shared__ float wsh[49 * 128];            // wsh[k][e_local]
    #pragma unroll 1
    for (int j = 0; j < 49; j++)
        wsh[j * 128 + threadIdx.x] = cw[(size_t)e * 49 + j];
    __syncthreads();

    const float bv = cb[e];
    const size_t rowbase = (size_t)b * L_;

    for (int s = 0; s < 64; s++) {
        const int yy = ty0 + (s >> 3);
        const int xx = tx0 + (s & 7);
        float acc = bv;
        #pragma unroll
        for (int ky = 0; ky < 7; ky++) {
            const int iy = yy + ky - 3;
            if (iy < 0 || iy >= H_) continue;
            #pragma unroll
            for (int kx = 0; kx < 7; kx++) {
                const int ix = xx + kx - 3;
                if (ix < 0 || ix >= W_) continue;
                acc = fmaf(xz[(rowbase + iy * W_ + ix) * (2 * E_) + e],
                           wsh[(ky * 7 + kx) * 128 + threadIdx.x], acc);
            }
        }
        const float sig = 1.f / (1.f + __expf(-acc));
        u[(rowbase + yy * W_ + xx) * E_ + e] = acc * sig;
    }
}

// ---------------- selective scan --------------------------------------------
// one warp = 2 e-channels of the same batch; 16 lanes = 16 states per channel.
__global__ __launch_bounds__(128) void scan_kernel(
    const float* __restrict__ delta, const float* __restrict__ u,
    const float* __restrict__ xdbl,  const float* __restrict__ A_log,
    const float* __restrict__ Dp,    float* __restrict__ y)
{
    const int warp = (blockIdx.x * blockDim.x + threadIdx.x) >> 5;
    const int lane = threadIdx.x & 31;
    const int half = lane >> 4;
    const int n    = lane & 15;
    const int b    = warp / (E_ / 2);
    const int e    = (warp % (E_ / 2)) * 2 + half;

    const float a  = -__expf(A_log[e * N_ + n]);
    const float dp = Dp[e];
    float s = 0.f;

    const float* dptr = delta + (size_t)b * L_ * E_ + e;
    const float* uptr = u     + (size_t)b * L_ * E_ + e;
    const float* xptr = xdbl  + (size_t)b * L_ * XD_ + R_ + n;   // B at +0, C at +N_
    float*       yptr = y     + (size_t)b * L_ * E_ + e;

    for (int t = 0; t < L_; t++) {
        const float d  = __ldg(dptr);
        const float uv = __ldg(uptr);
        const float Bn = __ldg(xptr);
        const float Cn = __ldg(xptr + N_);
        s = fmaf(s, __expf(d * a), (d * uv) * Bn);
        float v = s * Cn;
        v += __shfl_xor_sync(0xffffffffu, v, 1);
        v += __shfl_xor_sync(0xffffffffu, v, 2);
        v += __shfl_xor_sync(0xffffffffu, v, 4);
        v += __shfl_xor_sync(0xffffffffu, v, 8);
        if (n == 0) *yptr = fmaf(uv, dp, v);
        dptr += E_; uptr += E_; xptr += XD_; yptr += E_;
    }
}

// ---------------- batch-sum + gate: g[b,t,e] = (sum_b y) * silu(z[b,t,e]) ----
__global__ __launch_bounds__(256) void gate_kernel(
    const float* __restrict__ y, const float* __restrict__ xz,
    float* __restrict__ g)
{
    const int idx = blockIdx.x * blockDim.x + threadIdx.x;   // over L_*E_
    if (idx >= L_ * E_) return;
    float ssum = 0.f;
    #pragma unroll
    for (int b = 0; b < BATCH_; b++)
        ssum += y[((size_t)b * L_ * E_) + idx];
    const int t = idx / E_;
    const int e = idx - t * E_;
    #pragma unroll
    for (int b = 0; b < BATCH_; b++) {
        const float zv = xz[((size_t)(b * L_ + t)) * (2 * E_) + E_ + e];
        const float sig = 1.f / (1.f + __expf(-zv));
        g[((size_t)b * L_ * E_) + idx] = ssum * zv * sig;
    }
}

// ---------------- launch ------------------------------------------------------
extern "C" void kernel_launch(void* const* d_in, const int* in_sizes, int n_in,
                              void* d_out, int out_size)
{
    // metadata order: x, H, W, W_in, conv_w, conv_b, W_x, W_dt, b_dt, A_log, Dp, W_out.
    // Defensive: if H/W scalars were dropped, W_in sits at index 1 (size 768*192).
    int base = 3;
    if (in_sizes[1] == 2 * E_ * DM_) base = 1;

    const float* x      = (const float*)d_in[0];
    const float* W_in   = (const float*)d_in[base + 0];
    const float* conv_w = (const float*)d_in[base + 1];
    const float* conv_b = (const float*)d_in[base + 2];
    const float* W_x    = (const float*)d_in[base + 3];
    const float* W_dt   = (const float*)d_in[base + 4];
    const float* b_dt   = (const float*)d_in[base + 5];
    const float* A_log  = (const float*)d_in[base + 6];
    const float* Dp     = (const float*)d_in[base + 7];
    const float* W_out  = (const float*)d_in[base + 8];
    float* out = (float*)d_out;

    float *xz, *u, *xdbl, *delta, *y, *g;
    cudaGetSymbolAddress((void**)&xz,    g_xz);
    cudaGetSymbolAddress((void**)&u,     g_u);
    cudaGetSymbolAddress((void**)&xdbl,  g_xdbl);
    cudaGetSymbolAddress((void**)&delta, g_delta);
    cudaGetSymbolAddress((void**)&y,     g_y);
    cudaGetSymbolAddress((void**)&g,     g_g);

    // 1) xz = x @ W_in^T   (32768 x 192 -> 768)
    sgemm_nt<<<dim3(6, 256), 256>>>(x, DM_, W_in, DM_, xz, 2 * E_,
                                    ROWS_, 2 * E_, DM_, 0, nullptr);
    // 2) depthwise conv 7x7 + SiLU -> u
    dwconv_silu<<<dim3(3, 64, BATCH_), 128>>>(xz, conv_w, conv_b, u);
    // 3) x_dbl = u @ W_x^T  (-> 44)
    sgemm_nt<<<dim3(1, 256), 256>>>(u, E_, W_x, E_, xdbl, XD_,
                                    ROWS_, XD_, E_, 0, nullptr);
    // 4) delta = softplus(dt_r @ W_dt^T + 2*b_dt)   (K=12 -> 384)
    sgemm_nt<<<dim3(3, 256), 256>>>(xdbl, XD_, W_dt, R_, delta, E_,
                                    ROWS_, E_, R_, 1, b_dt);
    // 5) selective scan -> y (includes + u*Dp)
    scan_kernel<<<(BATCH_ * (E_ / 2)) / 4, 128>>>(delta, u, xdbl, A_log, Dp, y);
    // 6) batch-sum + SiLU gate -> g
    gate_kernel<<<(L_ * E_ + 255) / 256, 256>>>(y, xz, g);
    // 7) out = g @ W_out^T  (384 -> 192)
    sgemm_nt<<<dim3(2, 256), 256>>>(g, E_, W_out, E_, out, DM_,
                                    ROWS_, DM_, E_, 0, nullptr);
}

// round 2
// speedup vs baseline: 1.0825x; 1.0825x over previous
#include <cuda_runtime.h>

#define BATCH_ 8
#define H_ 64
#define W_ 64
#define L_ 4096          // H_*W_
#define DM_ 192          // d_model
#define E_ 384           // expanded inner dim
#define N_ 16            // d_state
#define R_ 12            // dt_rank
#define XD_ 44           // R_ + 2*N_
#define ROWS_ (BATCH_*L_) // 32768

// ---------------- scratch (device globals; no runtime allocation) -----------
__device__ float g_xz   [(size_t)ROWS_ * 2 * E_]; // in-proj output: [xs | z]
__device__ float g_u    [(size_t)ROWS_ * E_];     // conv+silu output
__device__ float g_xdbl [(size_t)ROWS_ * XD_];    // [dt_r | B | C]
__device__ float g_delta[(size_t)ROWS_ * E_];
__device__ float g_y    [(size_t)ROWS_ * E_];     // scan out + u*Dp
__device__ float g_g    [(size_t)ROWS_ * E_];     // gated (batch-summed) input to out-proj

// ============ double-buffered SGEMM: C[M,N] = A[M,K] * B[N,K]^T ==============
// BM=128, BK=16, 256 threads. BN=128 (TN=8) or BN=64 (TN=4).
// Requires: M % 128 == 0, K % 16 == 0. N arbitrary (guarded).
template<int BN, int TN>
__global__ __launch_bounds__(256) void sgemm_db(
    const float* __restrict__ A, int lda,
    const float* __restrict__ Bm, int ldb,
    float* __restrict__ C, int ldc,
    int M, int N, int K)
{
    constexpr int BM = 128, BK = 16, TM = 8;
    __shared__ float As[2][BK][BM];
    __shared__ float Bs[2][BK][BN];

    const int tid  = threadIdx.x;
    const int row0 = blockIdx.y * BM;
    const int col0 = blockIdx.x * BN;
    const int tx   = tid & 15;         // 16 col groups
    const int ty   = tid >> 4;         // 16 row groups

    // global-load mapping
    const int ar = tid >> 2;           // 0..63
    const int ak = (tid & 3) << 2;     // 0,4,8,12

    float acc[TM][TN];
    #pragma unroll
    for (int i = 0; i < TM; i++)
        #pragma unroll
        for (int j = 0; j < TN; j++) acc[i][j] = 0.f;

    const int nk = K / BK;

    float4 ra0, ra1, rb0, rb1;

    // ---- load tile kt into registers ----
    auto ldA = [&](int kt) {
        const float* p = A + (size_t)(row0 + ar) * lda + kt * BK + ak;
        ra0 = *reinterpret_cast<const float4*>(p);
        ra1 = *reinterpret_cast<const float4*>(p + (size_t)64 * lda);
    };
    auto ldB = [&](int kt) {
        const float4 z4 = make_float4(0.f, 0.f, 0.f, 0.f);
        int r = col0 + ar;
        rb0 = (r < N) ? *reinterpret_cast<const float4*>(Bm + (size_t)r * ldb + kt * BK + ak) : z4;
        if (BN == 128) {
            int r2 = r + 64;
            rb1 = (r2 < N) ? *reinterpret_cast<const float4*>(Bm + (size_t)r2 * ldb + kt * BK + ak) : z4;
        }
    };
    auto stSmem = [&](int buf) {
        As[buf][ak + 0][ar] = ra0.x; As[buf][ak + 1][ar] = ra0.y;
        As[buf][ak + 2][ar] = ra0.z; As[buf][ak + 3][ar] = ra0.w;
        As[buf][ak + 0][ar + 64] = ra1.x; As[buf][ak + 1][ar + 64] = ra1.y;
        As[buf][ak + 2][ar + 64] = ra1.z; As[buf][ak + 3][ar + 64] = ra1.w;
        Bs[buf][ak + 0][ar] = rb0.x; Bs[buf][ak + 1][ar] = rb0.y;
        Bs[buf][ak + 2][ar] = rb0.z; Bs[buf][ak + 3][ar] = rb0.w;
        if (BN == 128) {
            Bs[buf][ak + 0][ar + 64] = rb1.x; Bs[buf][ak + 1][ar + 64] = rb1.y;
            Bs[buf][ak + 2][ar + 64] = rb1.z; Bs[buf][ak + 3][ar + 64] = rb1.w;
        }
    };
    auto compute = [&](int buf) {
        #pragma unroll
        for (int kk = 0; kk < BK; kk++) {
            float a[TM], b[TN];
            float4 a0 = *reinterpret_cast<const float4*>(&As[buf][kk][ty * TM]);
            float4 a1 = *reinterpret_cast<const float4*>(&As[buf][kk][ty * TM + 4]);
            a[0] = a0.x; a[1] = a0.y; a[2] = a0.z; a[3] = a0.w;
            a[4] = a1.x; a[5] = a1.y; a[6] = a1.z; a[7] = a1.w;
            float4 b0 = *reinterpret_cast<const float4*>(&Bs[buf][kk][tx * TN]);
            b[0] = b0.x; b[1] = b0.y; b[2] = b0.z; b[3] = b0.w;
            if (TN == 8) {
                float4 b1 = *reinterpret_cast<const float4*>(&Bs[buf][kk][tx * TN + 4]);
                b[4] = b1.x; b[5] = b1.y; b[6] = b1.z; b[7] = b1.w;
            }
            #pragma unroll
            for (int i = 0; i < TM; i++)
                #pragma unroll
                for (int j = 0; j < TN; j++)
                    acc[i][j] = fmaf(a[i], b[j], acc[i][j]);
        }
    };

    ldA(0); ldB(0);
    stSmem(0);
    __syncthreads();

    for (int kt = 0; kt < nk; kt++) {
        const int cur = kt & 1;
        if (kt + 1 < nk) { ldA(kt + 1); ldB(kt + 1); }
        compute(cur);
        if (kt + 1 < nk) stSmem(cur ^ 1);
        __syncthreads();
    }

    // epilogue
    #pragma unroll
    for (int i = 0; i < TM; i++) {
        const int row = row0 + ty * TM + i;
        const int cb  = col0 + tx * TN;
        float* cp = C + (size_t)row * ldc + cb;
        if (cb + TN <= N) {
            #pragma unroll
            for (int j = 0; j < TN; j += 4)
                *reinterpret_cast<float4*>(cp + j) =
                    make_float4(acc[i][j], acc[i][j+1], acc[i][j+2], acc[i][j+3]);
        } else {
            #pragma unroll
            for (int j = 0; j < TN; j++)
                if (cb + j < N) cp[j] = acc[i][j];
        }
    }
}

// ============ delta = softplus(dt_r @ W_dt^T + 2*b_dt) =======================
// one block = 32 rows, 384 threads (one per output channel e)
__global__ __launch_bounds__(384) void dt_kernel(
    const float* __restrict__ xdbl, const float* __restrict__ W_dt,
    const float* __restrict__ b_dt, float* __restrict__ delta)
{
    __shared__ float wsh[E_ * R_];   // W_dt row-major copy
    __shared__ float dsh[32][R_];
    const int e = threadIdx.x;

    for (int i = e; i < E_ * R_; i += 384) wsh[i] = W_dt[i];

    const int row0 = blockIdx.x * 32;
    {   // 384 threads load 32 rows x 12 dt_r values
        const int r = e / R_, k = e - r * R_;
        dsh[r][k] = xdbl[(size_t)(row0 + r) * XD_ + k];
    }
    __syncthreads();

    float w[R_];
    #pragma unroll
    for (int k = 0; k < R_; k++) w[k] = wsh[e * R_ + k];
    const float b2 = 2.f * b_dt[e];

    #pragma unroll 4
    for (int r = 0; r < 32; r++) {
        float acc = b2;
        #pragma unroll
        for (int k = 0; k < R_; k++) acc = fmaf(dsh[r][k], w[k], acc);
        const float v = (acc > 20.f) ? acc : log1pf(__expf(acc));
        delta[(size_t)(row0 + r) * E_ + e] = v;
    }
}

// ---------------- depthwise 7x7 conv + bias + SiLU, channel-last -------------
__global__ __launch_bounds__(128) void dwconv_silu(
    const float* __restrict__ xz, const float* __restrict__ cw,
    const float* __restrict__ cb, float* __restrict__ u)
{
    const int ec0 = blockIdx.x * 128;
    const int e   = ec0 + threadIdx.x;
    const int ty0 = (blockIdx.y / (W_ / 8)) * 8;
    const int tx0 = (blockIdx.y % (W_ / 8)) * 8;
    const int b   = blockIdx.z;

    __shared__ float wsh[49 * 128];
    #pragma unroll 1
    for (int j = 0; j < 49; j++)
        wsh[j * 128 + threadIdx.x] = cw[(size_t)e * 49 + j];
    __syncthreads();

    const float bv = cb[e];
    const size_t rowbase = (size_t)b * L_;

    for (int s = 0; s < 64; s++) {
        const int yy = ty0 + (s >> 3);
        const int xx = tx0 + (s & 7);
        float acc = bv;
        #pragma unroll
        for (int ky = 0; ky < 7; ky++) {
            const int iy = yy + ky - 3;
            if (iy < 0 || iy >= H_) continue;
            #pragma unroll
            for (int kx = 0; kx < 7; kx++) {
                const int ix = xx + kx - 3;
                if (ix < 0 || ix >= W_) continue;
                acc = fmaf(xz[(rowbase + iy * W_ + ix) * (2 * E_) + e],
                           wsh[(ky * 7 + kx) * 128 + threadIdx.x], acc);
            }
        }
        const float sig = 1.f / (1.f + __expf(-acc));
        u[(rowbase + yy * W_ + xx) * E_ + e] = acc * sig;
    }
}

// ---------------- selective scan (unroll 4) ----------------------------------
__global__ __launch_bounds__(128) void scan_kernel(
    const float* __restrict__ delta, const float* __restrict__ u,
    const float* __restrict__ xdbl,  const float* __restrict__ A_log,
    const float* __restrict__ Dp,    float* __restrict__ y)
{
    const int warp = (blockIdx.x * blockDim.x + threadIdx.x) >> 5;
    const int lane = threadIdx.x & 31;
    const int half = lane >> 4;
    const int n    = lane & 15;
    const int b    = warp / (E_ / 2);
    const int e    = (warp % (E_ / 2)) * 2 + half;

    const float a  = -__expf(A_log[e * N_ + n]);
    const float dp = Dp[e];
    float s = 0.f;

    const float* dptr = delta + (size_t)b * L_ * E_ + e;
    const float* uptr = u     + (size_t)b * L_ * E_ + e;
    const float* xptr = xdbl  + (size_t)b * L_ * XD_ + R_ + n;
    float*       yptr = y     + (size_t)b * L_ * E_ + e;

    for (int t = 0; t < L_; t += 4) {
        float d[4], uv[4], Bn[4], Cn[4];
        #pragma unroll
        for (int q = 0; q < 4; q++) {
            d[q]  = __ldg(dptr);
            uv[q] = __ldg(uptr);
            Bn[q] = __ldg(xptr);
            Cn[q] = __ldg(xptr + N_);
            dptr += E_; uptr += E_; xptr += XD_;
        }
        float v[4];
        #pragma unroll
        for (int q = 0; q < 4; q++) {
            s = fmaf(s, __expf(d[q] * a), (d[q] * uv[q]) * Bn[q]);
            v[q] = s * Cn[q];
        }
        #pragma unroll
        for (int q = 0; q < 4; q++) {
            v[q] += __shfl_xor_sync(0xffffffffu, v[q], 1);
            v[q] += __shfl_xor_sync(0xffffffffu, v[q], 2);
            v[q] += __shfl_xor_sync(0xffffffffu, v[q], 4);
            v[q] += __shfl_xor_sync(0xffffffffu, v[q], 8);
        }
        if (n == 0) {
            #pragma unroll
            for (int q = 0; q < 4; q++)
                yptr[q * E_] = fmaf(uv[q], dp, v[q]);
        }
        yptr += 4 * E_;
    }
}

// ---------------- batch-sum + gate -------------------------------------------
__global__ __launch_bounds__(256) void gate_kernel(
    const float* __restrict__ y, const float* __restrict__ xz,
    float* __restrict__ g)
{
    const int idx = blockIdx.x * blockDim.x + threadIdx.x;
    if (idx >= L_ * E_) return;
    float ssum = 0.f;
    #pragma unroll
    for (int b = 0; b < BATCH_; b++)
        ssum += y[((size_t)b * L_ * E_) + idx];
    const int t = idx / E_;
    const int e = idx - t * E_;
    #pragma unroll
    for (int b = 0; b < BATCH_; b++) {
        const float zv = xz[((size_t)(b * L_ + t)) * (2 * E_) + E_ + e];
        const float sig = 1.f / (1.f + __expf(-zv));
        g[((size_t)b * L_ * E_) + idx] = ssum * zv * sig;
    }
}

// ---------------- launch ------------------------------------------------------
extern "C" void kernel_launch(void* const* d_in, const int* in_sizes, int n_in,
                              void* d_out, int out_size)
{
    int base = 3;
    if (in_sizes[1] == 2 * E_ * DM_) base = 1;

    const float* x      = (const float*)d_in[0];
    const float* W_in   = (const float*)d_in[base + 0];
    const float* conv_w = (const float*)d_in[base + 1];
    const float* conv_b = (const float*)d_in[base + 2];
    const float* W_x    = (const float*)d_in[base + 3];
    const float* W_dt   = (const float*)d_in[base + 4];
    const float* b_dt   = (const float*)d_in[base + 5];
    const float* A_log  = (const float*)d_in[base + 6];
    const float* Dp     = (const float*)d_in[base + 7];
    const float* W_out  = (const float*)d_in[base + 8];
    float* out = (float*)d_out;

    float *xz, *u, *xdbl, *delta, *y, *g;
    cudaGetSymbolAddress((void**)&xz,    g_xz);
    cudaGetSymbolAddress((void**)&u,     g_u);
    cudaGetSymbolAddress((void**)&xdbl,  g_xdbl);
    cudaGetSymbolAddress((void**)&delta, g_delta);
    cudaGetSymbolAddress((void**)&y,     g_y);
    cudaGetSymbolAddress((void**)&g,     g_g);

    // 1) xz = x @ W_in^T   (32768 x 192 -> 768)
    sgemm_db<128, 8><<<dim3(6, 256), 256>>>(x, DM_, W_in, DM_, xz, 2 * E_,
                                            ROWS_, 2 * E_, DM_);
    // 2) depthwise conv 7x7 + SiLU -> u
    dwconv_silu<<<dim3(3, 64, BATCH_), 128>>>(xz, conv_w, conv_b, u);
    // 3) x_dbl = u @ W_x^T  (-> 44)
    sgemm_db<64, 4><<<dim3(1, 256), 256>>>(u, E_, W_x, E_, xdbl, XD_,
                                           ROWS_, XD_, E_);
    // 4) delta = softplus(dt_r @ W_dt^T + 2*b_dt)
    dt_kernel<<<ROWS_ / 32, 384>>>(xdbl, W_dt, b_dt, delta);
    // 5) selective scan -> y (includes + u*Dp)
    scan_kernel<<<(BATCH_ * (E_ / 2)) / 4, 128>>>(delta, u, xdbl, A_log, Dp, y);
    // 6) batch-sum + SiLU gate -> g
    gate_kernel<<<(L_ * E_ + 255) / 256, 256>>>(y, xz, g);
    // 7) out = g @ W_out^T  (384 -> 192)
    sgemm_db<64, 4><<<dim3(3, 256), 256>>>(g, E_, W_out, E_, out, DM_,
                                           ROWS_, DM_, E_);
}

// round 5
// speedup vs baseline: 1.1311x; 1.0449x over previous
#include <cuda_runtime.h>
#include <cuda_bf16.h>
#include <mma.h>
#include <cstdint>

using namespace nvcuda;

#define BATCH_ 8
#define H_ 64
#define W_ 64
#define L_ 4096
#define DM_ 192
#define E_ 384
#define N_ 16
#define R_ 12
#define XD_ 44
#define ROWS_ (BATCH_*L_)

// ---------------- cp.async helpers (Ampere-path, valid on sm_103) ------------
__device__ __forceinline__ uint32_t smem_u32(const void* p) {
    uint32_t a;
    asm("{ .reg .u64 t; cvta.to.shared.u64 t, %1; cvt.u32.u64 %0, t; }" : "=r"(a) : "l"(p));
    return a;
}
#define CP_ASYNC16(dst, src, szbytes) \
    asm volatile("cp.async.cg.shared.global [%0], [%1], 16, %2;" \
                 :: "r"(dst), "l"(src), "r"(szbytes))
#define CP_COMMIT() asm volatile("cp.async.commit_group;")
#define CP_WAIT1()  asm volatile("cp.async.wait_group 1;")

// ---------------- scratch ----------------------------------------------------
__device__ float g_xz   [(size_t)ROWS_ * 2 * E_];
__device__ float g_u    [(size_t)ROWS_ * E_];
__device__ float g_xdbl [(size_t)ROWS_ * XD_];
__device__ float g_delta[(size_t)ROWS_ * E_];
__device__ float g_y    [(size_t)ROWS_ * E_];
__device__ __nv_bfloat16 g_xaug [(size_t)ROWS_ * 3 * DM_];
__device__ __nv_bfloat16 g_uaug [(size_t)ROWS_ * 3 * E_];
__device__ __nv_bfloat16 g_gaug [(size_t)ROWS_ * 3 * E_];
__device__ __nv_bfloat16 g_wina [(size_t)(2*E_) * 3 * DM_];
__device__ __nv_bfloat16 g_wxa  [(size_t)XD_ * 3 * E_];
__device__ __nv_bfloat16 g_woa  [(size_t)DM_ * 3 * E_];

// ---------- hi/lo split.  variant 0 (activations): [hi | lo | hi]
//            variant 1 (weights):     [hi | hi | lo]
__global__ void split_bf16(const float* __restrict__ src, __nv_bfloat16* __restrict__ dst,
                           int rows, int K, int variant)
{
    int idx = blockIdx.x * 256 + threadIdx.x;
    if (idx >= rows * K) return;
    int r = idx / K, k = idx - r * K;
    float v = src[idx];
    __nv_bfloat16 hi = __float2bfloat16(v);
    __nv_bfloat16 lo = __float2bfloat16(v - __bfloat162float(hi));
    size_t base = (size_t)r * 3 * K + k;
    if (variant == 0) { dst[base] = hi; dst[base + K] = lo; dst[base + 2 * K] = hi; }
    else              { dst[base] = hi; dst[base + K] = hi; dst[base + 2 * K] = lo; }
}

// ============ WMMA bf16 GEMM: C[M,Nout] = Aaug[M,Kaug] * Baug[Nout,Kaug]^T ===
// 256 threads (8 warps). BM=128, BK=32. Warp tile 32 x (BN/2).
template<int BN, bool GUARDN>
__global__ __launch_bounds__(256) void wmma_gemm(
    const __nv_bfloat16* __restrict__ Aaug,
    const __nv_bfloat16* __restrict__ Baug,
    float* __restrict__ C, int ldc, int Kaug, int Nout)
{
    constexpr int BM = 128, BK = 32;
    constexpr int LDS = BK + 16;                // 48 bf16 = 96B rows (32B-aligned)
    constexpr int WNC = BN / 2;
    constexpr int NF  = WNC / 16;
    constexpr int ABYTES = 2 * BM * LDS * 2;
    constexpr int BBYTES = 2 * BN * LDS * 2;
    constexpr int SBYTES = (ABYTES + BBYTES) > (GUARDN ? BM * BN * 4 : 0)
                         ? (ABYTES + BBYTES) : BM * BN * 4;
    __shared__ __align__(32) char smem_raw[SBYTES];

    typedef __nv_bfloat16 ARow[BM][LDS];
    typedef __nv_bfloat16 BRow[BN][LDS];
    ARow* sA = reinterpret_cast<ARow*>(smem_raw);
    BRow* sB = reinterpret_cast<BRow*>(smem_raw + ABYTES);

    const int tid  = threadIdx.x;
    const int wid  = tid >> 5;
    const int wy   = wid & 3;
    const int wx   = wid >> 2;
    const int row0 = blockIdx.y * BM;
    const int col0 = blockIdx.x * BN;

    wmma::fragment<wmma::accumulator, 16, 16, 16, float> acc[2][NF];
    #pragma unroll
    for (int i = 0; i < 2; i++)
        #pragma unroll
        for (int j = 0; j < NF; j++) wmma::fill_fragment(acc[i][j], 0.f);

    const int nk = Kaug / BK;

    auto ld_tiles = [&](int kc, int buf) {
        #pragma unroll
        for (int it = 0; it < 2; it++) {
            int idx = it * 256 + tid;
            int r = idx >> 2, ck = idx & 3;
            const __nv_bfloat16* src = Aaug + (size_t)(row0 + r) * Kaug + kc * BK + ck * 8;
            CP_ASYNC16(smem_u32(&sA[buf][r][ck * 8]), src, 16);
        }
        #pragma unroll
        for (int it = 0; it < BN / 64; it++) {
            int idx = it * 256 + tid;
            int r = idx >> 2, ck = idx & 3;
            int n = col0 + r;
            const __nv_bfloat16* src = Baug + (size_t)n * Kaug + kc * BK + ck * 8;
            CP_ASYNC16(smem_u32(&sB[buf][r][ck * 8]), src, (n < Nout) ? 16 : 0);
        }
    };

    ld_tiles(0, 0);
    CP_COMMIT();

    for (int kt = 0; kt < nk; kt++) {
        const int buf = kt & 1;
        if (kt + 1 < nk) ld_tiles(kt + 1, buf ^ 1);
        CP_COMMIT();
        CP_WAIT1();
        __syncthreads();

        #pragma unroll
        for (int ks = 0; ks < 2; ks++) {
            wmma::fragment<wmma::matrix_a, 16, 16, 16, __nv_bfloat16, wmma::row_major> af[2];
            wmma::fragment<wmma::matrix_b, 16, 16, 16, __nv_bfloat16, wmma::col_major> bf[NF];
            #pragma unroll
            for (int i = 0; i < 2; i++)
                wmma::load_matrix_sync(af[i], &sA[buf][wy * 32 + i * 16][ks * 16], LDS);
            #pragma unroll
            for (int j = 0; j < NF; j++)
                wmma::load_matrix_sync(bf[j], &sB[buf][wx * WNC + j * 16][ks * 16], LDS);
            #pragma unroll
            for (int i = 0; i < 2; i++)
                #pragma unroll
                for (int j = 0; j < NF; j++)
                    wmma::mma_sync(acc[i][j], af[i], bf[j], acc[i][j]);
        }
        __syncthreads();
    }

    if (!GUARDN) {
        #pragma unroll
        for (int i = 0; i < 2; i++)
            #pragma unroll
            for (int j = 0; j < NF; j++)
                wmma::store_matrix_sync(
                    C + (size_t)(row0 + wy * 32 + i * 16) * ldc + col0 + wx * WNC + j * 16,
                    acc[i][j], ldc, wmma::mem_row_major);
    } else {
        float* stage = reinterpret_cast<float*>(smem_raw);
        __syncthreads();
        #pragma unroll
        for (int i = 0; i < 2; i++)
            #pragma unroll
            for (int j = 0; j < NF; j++)
                wmma::store_matrix_sync(
                    stage + (size_t)(wy * 32 + i * 16) * BN + wx * WNC + j * 16,
                    acc[i][j], BN, wmma::mem_row_major);
        __syncthreads();
        for (int idx = tid; idx < BM * BN; idx += 256) {
            int r = idx / BN, c = idx - r * BN;
            if (col0 + c < Nout)
                C[(size_t)(row0 + r) * ldc + col0 + c] = stage[idx];
        }
    }
}

// ================= delta = softplus(dt_r @ W_dt^T + 2*b_dt) ==================
__global__ __launch_bounds__(384) void dt_kernel(
    const float* __restrict__ xdbl, const float* __restrict__ W_dt,
    const float* __restrict__ b_dt, float* __restrict__ delta)
{
    __shared__ float wsh[E_ * R_];
    __shared__ float dsh[32][R_];
    const int e = threadIdx.x;
    for (int i = e; i < E_ * R_; i += 384) wsh[i] = W_dt[i];
    const int row0 = blockIdx.x * 32;
    {
        const int r = e / R_, k = e - r * R_;
        dsh[r][k] = xdbl[(size_t)(row0 + r) * XD_ + k];
    }
    __syncthreads();
    float w[R_];
    #pragma unroll
    for (int k = 0; k < R_; k++) w[k] = wsh[e * R_ + k];
    const float b2 = 2.f * b_dt[e];
    #pragma unroll 4
    for (int r = 0; r < 32; r++) {
        float acc = b2;
        #pragma unroll
        for (int k = 0; k < R_; k++) acc = fmaf(dsh[r][k], w[k], acc);
        delta[(size_t)(row0 + r) * E_ + e] = (acc > 20.f) ? acc : log1pf(__expf(acc));
    }
}

// ================= depthwise 7x7 conv + bias + SiLU; writes u fp32 + u_aug ===
__global__ __launch_bounds__(128) void dwconv_silu(
    const float* __restrict__ xz, const float* __restrict__ cw,
    const float* __restrict__ cb, float* __restrict__ u,
    __nv_bfloat16* __restrict__ uaug)
{
    const int e   = blockIdx.x * 128 + threadIdx.x;
    const int ty0 = (blockIdx.y / (W_ / 8)) * 8;
    const int tx0 = (blockIdx.y % (W_ / 8)) * 8;
    const int b   = blockIdx.z;

    __shared__ float wsh[49 * 128];
    #pragma unroll 1
    for (int j = 0; j < 49; j++)
        wsh[j * 128 + threadIdx.x] = cw[(size_t)e * 49 + j];
    __syncthreads();

    const float bv = cb[e];
    const size_t rowbase = (size_t)b * L_;

    for (int s = 0; s < 64; s++) {
        const int yy = ty0 + (s >> 3);
        const int xx = tx0 + (s & 7);
        float acc = bv;
        #pragma unroll
        for (int ky = 0; ky < 7; ky++) {
            const int iy = yy + ky - 3;
            if (iy < 0 || iy >= H_) continue;
            #pragma unroll
            for (int kx = 0; kx < 7; kx++) {
                const int ix = xx + kx - 3;
                if (ix < 0 || ix >= W_) continue;
                acc = fmaf(xz[(rowbase + iy * W_ + ix) * (2 * E_) + e],
                           wsh[(ky * 7 + kx) * 128 + threadIdx.x], acc);
            }
        }
        const float sig = 1.f / (1.f + __expf(-acc));
        const float v = acc * sig;
        const size_t row = rowbase + yy * W_ + xx;
        u[row * E_ + e] = v;
        __nv_bfloat16 hi = __float2bfloat16(v);
        __nv_bfloat16 lo = __float2bfloat16(v - __bfloat162float(hi));
        const size_t ab = row * (3 * E_) + e;
        uaug[ab] = hi; uaug[ab + E_] = lo; uaug[ab + 2 * E_] = hi;
    }
}

// ================= selective scan ============================================
__global__ __launch_bounds__(128) void scan_kernel(
    const float* __restrict__ delta, const float* __restrict__ u,
    const float* __restrict__ xdbl,  const float* __restrict__ A_log,
    const float* __restrict__ Dp,    float* __restrict__ y)
{
    const int warp = (blockIdx.x * blockDim.x + threadIdx.x) >> 5;
    const int lane = threadIdx.x & 31;
    const int half = lane >> 4;
    const int n    = lane & 15;
    const int b    = warp / (E_ / 2);
    const int e    = (warp % (E_ / 2)) * 2 + half;

    const float a  = -__expf(A_log[e * N_ + n]);
    const float dp = Dp[e];
    float s = 0.f;

    const float* dptr = delta + (size_t)b * L_ * E_ + e;
    const float* uptr = u     + (size_t)b * L_ * E_ + e;
    const float* xptr = xdbl  + (size_t)b * L_ * XD_ + R_ + n;
    float*       yptr = y     + (size_t)b * L_ * E_ + e;

    for (int t = 0; t < L_; t += 4) {
        float d[4], uv[4], Bn[4], Cn[4];
        #pragma unroll
        for (int q = 0; q < 4; q++) {
            d[q]  = __ldg(dptr); uv[q] = __ldg(uptr);
            Bn[q] = __ldg(xptr); Cn[q] = __ldg(xptr + N_);
            dptr += E_; uptr += E_; xptr += XD_;
        }
        float v[4];
        #pragma unroll
        for (int q = 0; q < 4; q++) {
            s = fmaf(s, __expf(d[q] * a), (d[q] * uv[q]) * Bn[q]);
            v[q] = s * Cn[q];
        }
        #pragma unroll
        for (int q = 0; q < 4; q++) {
            v[q] += __shfl_xor_sync(0xffffffffu, v[q], 1);
            v[q] += __shfl_xor_sync(0xffffffffu, v[q], 2);
            v[q] += __shfl_xor_sync(0xffffffffu, v[q], 4);
            v[q] += __shfl_xor_sync(0xffffffffu, v[q], 8);
        }
        if (n == 0) {
            #pragma unroll
            for (int q = 0; q < 4; q++)
                yptr[q * E_] = fmaf(uv[q], dp, v[q]);
        }
        yptr += 4 * E_;
    }
}

// ================= batch-sum + gate -> g_aug =================================
__global__ __launch_bounds__(256) void gate_kernel(
    const float* __restrict__ y, const float* __restrict__ xz,
    __nv_bfloat16* __restrict__ gaug)
{
    const int idx = blockIdx.x * blockDim.x + threadIdx.x;
    if (idx >= L_ * E_) return;
    float ssum = 0.f;
    #pragma unroll
    for (int b = 0; b < BATCH_; b++)
        ssum += y[((size_t)b * L_ * E_) + idx];
    const int t = idx / E_;
    const int e = idx - t * E_;
    #pragma unroll
    for (int b = 0; b < BATCH_; b++) {
        const float zv = xz[((size_t)(b * L_ + t)) * (2 * E_) + E_ + e];
        const float sig = 1.f / (1.f + __expf(-zv));
        const float v = ssum * zv * sig;
        __nv_bfloat16 hi = __float2bfloat16(v);
        __nv_bfloat16 lo = __float2bfloat16(v - __bfloat162float(hi));
        const size_t ab = ((size_t)(b * L_ + t)) * (3 * E_) + e;
        gaug[ab] = hi; gaug[ab + E_] = lo; gaug[ab + 2 * E_] = hi;
    }
}

// ================= launch =====================================================
extern "C" void kernel_launch(void* const* d_in, const int* in_sizes, int n_in,
                              void* d_out, int out_size)
{
    int base = 3;
    if (in_sizes[1] == 2 * E_ * DM_) base = 1;

    const float* x      = (const float*)d_in[0];
    const float* W_in   = (const float*)d_in[base + 0];
    const float* conv_w = (const float*)d_in[base + 1];
    const float* conv_b = (const float*)d_in[base + 2];
    const float* W_x    = (const float*)d_in[base + 3];
    const float* W_dt   = (const float*)d_in[base + 4];
    const float* b_dt   = (const float*)d_in[base + 5];
    const float* A_log  = (const float*)d_in[base + 6];
    const float* Dp     = (const float*)d_in[base + 7];
    const float* W_out  = (const float*)d_in[base + 8];
    float* out = (float*)d_out;

    float *xz, *u, *xdbl, *delta, *y;
    __nv_bfloat16 *xaug, *uaug, *gaug, *wina, *wxa, *woa;
    cudaGetSymbolAddress((void**)&xz,    g_xz);
    cudaGetSymbolAddress((void**)&u,     g_u);
    cudaGetSymbolAddress((void**)&xdbl,  g_xdbl);
    cudaGetSymbolAddress((void**)&delta, g_delta);
    cudaGetSymbolAddress((void**)&y,     g_y);
    cudaGetSymbolAddress((void**)&xaug,  g_xaug);
    cudaGetSymbolAddress((void**)&uaug,  g_uaug);
    cudaGetSymbolAddress((void**)&gaug,  g_gaug);
    cudaGetSymbolAddress((void**)&wina,  g_wina);
    cudaGetSymbolAddress((void**)&wxa,   g_wxa);
    cudaGetSymbolAddress((void**)&woa,   g_woa);

    // converts: activations variant 0 [hi|lo|hi], weights variant 1 [hi|hi|lo]
    split_bf16<<<(ROWS_ * DM_ + 255) / 256, 256>>>(x, xaug, ROWS_, DM_, 0);
    split_bf16<<<(2 * E_ * DM_ + 255) / 256, 256>>>(W_in, wina, 2 * E_, DM_, 1);
    split_bf16<<<(XD_ * E_ + 255) / 256, 256>>>(W_x, wxa, XD_, E_, 1);
    split_bf16<<<(DM_ * E_ + 255) / 256, 256>>>(W_out, woa, DM_, E_, 1);

    // 1) xz = x @ W_in^T   (Kaug=576, N=768)
    wmma_gemm<128, false><<<dim3(6, ROWS_ / 128), 256>>>(xaug, wina, xz, 2 * E_, 3 * DM_, 2 * E_);
    // 2) conv + silu -> u, u_aug
    dwconv_silu<<<dim3(3, 64, BATCH_), 128>>>(xz, conv_w, conv_b, u, uaug);
    // 3) x_dbl = u @ W_x^T  (Kaug=1152, N=44, guarded)
    wmma_gemm<64, true><<<dim3(1, ROWS_ / 128), 256>>>(uaug, wxa, xdbl, XD_, 3 * E_, XD_);
    // 4) delta
    dt_kernel<<<ROWS_ / 32, 384>>>(xdbl, W_dt, b_dt, delta);
    // 5) scan
    scan_kernel<<<(BATCH_ * (E_ / 2)) / 4, 128>>>(delta, u, xdbl, A_log, Dp, y);
    // 6) gate -> g_aug
    gate_kernel<<<(L_ * E_ + 255) / 256, 256>>>(y, xz, gaug);
    // 7) out = g @ W_out^T  (Kaug=1152, N=192)
    wmma_gemm<64, false><<<dim3(3, ROWS_ / 128), 256>>>(gaug, woa, out, DM_, 3 * E_, DM_);
}

// round 6
// speedup vs baseline: 1.9519x; 1.7257x over previous
#include <cuda_runtime.h>
#include <cuda_bf16.h>
#include <mma.h>
#include <cstdint>

using namespace nvcuda;

#define BATCH_ 8
#define H_ 64
#define W_ 64
#define L_ 4096
#define DM_ 192
#define E_ 384
#define N_ 16
#define R_ 12
#define XD_ 44
#define ROWS_ (BATCH_*L_)

// ---------------- cp.async helpers ------------------------------------------
__device__ __forceinline__ uint32_t smem_u32(const void* p) {
    uint32_t a;
    asm("{ .reg .u64 t; cvta.to.shared.u64 t, %1; cvt.u32.u64 %0, t; }" : "=r"(a) : "l"(p));
    return a;
}
#define CP_ASYNC16(dst, src, szbytes) \
    asm volatile("cp.async.cg.shared.global [%0], [%1], 16, %2;" \
                 :: "r"(dst), "l"(src), "r"(szbytes))
#define CP_COMMIT() asm volatile("cp.async.commit_group;")
#define CP_WAIT1()  asm volatile("cp.async.wait_group 1;")

// ---------------- scratch ----------------------------------------------------
__device__ float g_xz   [(size_t)ROWS_ * 2 * E_];
__device__ float g_ut   [(size_t)ROWS_ * E_];     // u transposed [b][e][t]
__device__ float g_xdbl [(size_t)ROWS_ * XD_];
__device__ float g_dt   [(size_t)ROWS_ * E_];     // delta transposed [b][e][t]
__device__ float g_y    [(size_t)ROWS_ * E_];     // [b][t][e]
__device__ __nv_bfloat16 g_xaug [(size_t)ROWS_ * 3 * DM_];
__device__ __nv_bfloat16 g_uaug [(size_t)ROWS_ * 3 * E_];
__device__ __nv_bfloat16 g_gaug [(size_t)ROWS_ * 3 * E_];
__device__ __nv_bfloat16 g_wina [(size_t)(2*E_) * 3 * DM_];
__device__ __nv_bfloat16 g_wxa  [(size_t)XD_ * 3 * E_];
__device__ __nv_bfloat16 g_woa  [(size_t)DM_ * 3 * E_];

// ---------- hi/lo split. variant 0 (activations): [hi|lo|hi]; 1 (weights): [hi|hi|lo]
__global__ void split_bf16(const float* __restrict__ src, __nv_bfloat16* __restrict__ dst,
                           int rows, int K, int variant)
{
    int idx = blockIdx.x * 256 + threadIdx.x;
    if (idx >= rows * K) return;
    int r = idx / K, k = idx - r * K;
    float v = src[idx];
    __nv_bfloat16 hi = __float2bfloat16(v);
    __nv_bfloat16 lo = __float2bfloat16(v - __bfloat162float(hi));
    size_t base = (size_t)r * 3 * K + k;
    if (variant == 0) { dst[base] = hi; dst[base + K] = lo; dst[base + 2 * K] = hi; }
    else              { dst[base] = hi; dst[base + K] = hi; dst[base + 2 * K] = lo; }
}

// ============ WMMA bf16 GEMM, 4 warps, warp tile 64 x (NFR*16) ================
// CTA tile 128 x (NFR*32). BK=32 double-buffered cp.async. 128 threads.
template<int NFR, bool GUARDN>
__global__ __launch_bounds__(128) void wmma_gemm(
    const __nv_bfloat16* __restrict__ Aaug,
    const __nv_bfloat16* __restrict__ Baug,
    float* __restrict__ C, int ldc, int Kaug, int Nout)
{
    constexpr int BM = 128, BK = 32;
    constexpr int BN = NFR * 32;
    constexpr int WNC = BN / 2;
    constexpr int LDS = BK + 16;                // 48 bf16 = 96B rows
    constexpr int ABYTES = 2 * BM * LDS * 2;
    constexpr int BBYTES = 2 * BN * LDS * 2;
    constexpr int AB = ABYTES + BBYTES;
    constexpr int SBYTES = (GUARDN && BM * BN * 4 > AB) ? BM * BN * 4 : AB;
    __shared__ __align__(32) char smem_raw[SBYTES];

    typedef __nv_bfloat16 ARow[BM][LDS];
    typedef __nv_bfloat16 BRow[BN][LDS];
    ARow* sA = reinterpret_cast<ARow*>(smem_raw);
    BRow* sB = reinterpret_cast<BRow*>(smem_raw + ABYTES);

    const int tid  = threadIdx.x;
    const int wid  = tid >> 5;
    const int wy   = wid & 1;
    const int wx   = wid >> 1;
    const int row0 = blockIdx.y * BM;
    const int col0 = blockIdx.x * BN;

    wmma::fragment<wmma::accumulator, 16, 16, 16, float> acc[4][NFR];
    #pragma unroll
    for (int i = 0; i < 4; i++)
        #pragma unroll
        for (int j = 0; j < NFR; j++) wmma::fill_fragment(acc[i][j], 0.f);

    const int nk = Kaug / BK;

    auto ld_tiles = [&](int kc, int buf) {
        #pragma unroll
        for (int it = 0; it < 4; it++) {              // A: 512 cp ops / 128 thr
            int idx = it * 128 + tid;
            int r = idx >> 2, ck = idx & 3;
            const __nv_bfloat16* src = Aaug + (size_t)(row0 + r) * Kaug + kc * BK + ck * 8;
            CP_ASYNC16(smem_u32(&sA[buf][r][ck * 8]), src, 16);
        }
        #pragma unroll
        for (int it = 0; it < NFR; it++) {            // B: BN*4 ops
            int idx = it * 128 + tid;
            int r = idx >> 2, ck = idx & 3;
            int n = col0 + r;
            const __nv_bfloat16* src = Baug + (size_t)n * Kaug + kc * BK + ck * 8;
            CP_ASYNC16(smem_u32(&sB[buf][r][ck * 8]), src, (n < Nout) ? 16 : 0);
        }
    };

    ld_tiles(0, 0);
    CP_COMMIT();

    for (int kt = 0; kt < nk; kt++) {
        const int buf = kt & 1;
        if (kt + 1 < nk) ld_tiles(kt + 1, buf ^ 1);
        CP_COMMIT();
        CP_WAIT1();
        __syncthreads();

        #pragma unroll
        for (int ks = 0; ks < 2; ks++) {
            wmma::fragment<wmma::matrix_a, 16, 16, 16, __nv_bfloat16, wmma::row_major> af[4];
            wmma::fragment<wmma::matrix_b, 16, 16, 16, __nv_bfloat16, wmma::col_major> bf[NFR];
            #pragma unroll
            for (int i = 0; i < 4; i++)
                wmma::load_matrix_sync(af[i], &sA[buf][wy * 64 + i * 16][ks * 16], LDS);
            #pragma unroll
            for (int j = 0; j < NFR; j++)
                wmma::load_matrix_sync(bf[j], &sB[buf][wx * WNC + j * 16][ks * 16], LDS);
            #pragma unroll
            for (int i = 0; i < 4; i++)
                #pragma unroll
                for (int j = 0; j < NFR; j++)
                    wmma::mma_sync(acc[i][j], af[i], bf[j], acc[i][j]);
        }
        __syncthreads();
    }

    if (!GUARDN) {
        // fragment-granularity column skip (Nout must be multiple of 16 per valid frag)
        #pragma unroll
        for (int i = 0; i < 4; i++)
            #pragma unroll
            for (int j = 0; j < NFR; j++) {
                int cc = col0 + wx * WNC + j * 16;
                if (cc + 16 <= Nout)
                    wmma::store_matrix_sync(
                        C + (size_t)(row0 + wy * 64 + i * 16) * ldc + cc,
                        acc[i][j], ldc, wmma::mem_row_major);
            }
    } else {
        float* stage = reinterpret_cast<float*>(smem_raw);
        __syncthreads();
        #pragma unroll
        for (int i = 0; i < 4; i++)
            #pragma unroll
            for (int j = 0; j < NFR; j++)
                wmma::store_matrix_sync(
                    stage + (size_t)(wy * 64 + i * 16) * BN + wx * WNC + j * 16,
                    acc[i][j], BN, wmma::mem_row_major);
        __syncthreads();
        for (int idx = tid; idx < BM * BN; idx += 128) {
            int r = idx / BN, c = idx - r * BN;
            if (col0 + c < Nout)
                C[(size_t)(row0 + r) * ldc + col0 + c] = stage[idx];
        }
    }
}

// ============ delta = softplus(dt_r @ W_dt^T + 2*b_dt), transposed out ========
__global__ __launch_bounds__(384) void dt_kernel(
    const float* __restrict__ xdbl, const float* __restrict__ W_dt,
    const float* __restrict__ b_dt, float* __restrict__ delta_t)
{
    __shared__ float wsh[E_ * R_];
    __shared__ float dsh[32][R_];
    const int e = threadIdx.x;
    for (int i = e; i < E_ * R_; i += 384) wsh[i] = W_dt[i];
    const int row0 = blockIdx.x * 32;
    const int b  = row0 >> 12;
    const int t0 = row0 & (L_ - 1);
    {
        const int r = e / R_, k = e - r * R_;
        dsh[r][k] = xdbl[(size_t)(row0 + r) * XD_ + k];
    }
    __syncthreads();
    float w[R_];
    #pragma unroll
    for (int k = 0; k < R_; k++) w[k] = wsh[e * R_ + k];
    const float b2 = 2.f * b_dt[e];
    float out[32];
    #pragma unroll 4
    for (int r = 0; r < 32; r++) {
        float acc = b2;
        #pragma unroll
        for (int k = 0; k < R_; k++) acc = fmaf(dsh[r][k], w[k], acc);
        out[r] = (acc > 20.f) ? acc : log1pf(__expf(acc));
    }
    float4* dst = reinterpret_cast<float4*>(delta_t + ((size_t)b * E_ + e) * L_ + t0);
    #pragma unroll
    for (int q = 0; q < 8; q++)
        dst[q] = make_float4(out[4*q], out[4*q+1], out[4*q+2], out[4*q+3]);
}

// ============ depthwise 7x7 conv + SiLU; writes u_t [b][e][t] + uaug ==========
__global__ __launch_bounds__(128) void dwconv_silu(
    const float* __restrict__ xz, const float* __restrict__ cw,
    const float* __restrict__ cb, float* __restrict__ u_t,
    __nv_bfloat16* __restrict__ uaug)
{
    const int e   = blockIdx.x * 128 + threadIdx.x;
    const int ty0 = (blockIdx.y / (W_ / 8)) * 8;
    const int tx0 = (blockIdx.y % (W_ / 8)) * 8;
    const int b   = blockIdx.z;

    __shared__ float wsh[49 * 128];
    #pragma unroll 1
    for (int j = 0; j < 49; j++)
        wsh[j * 128 + threadIdx.x] = cw[(size_t)e * 49 + j];
    __syncthreads();

    const float bv = cb[e];
    const size_t rowbase = (size_t)b * L_;
    float* utbase = u_t + ((size_t)b * E_ + e) * L_;

    #pragma unroll 1
    for (int ry = 0; ry < 8; ry++) {
        const int yy = ty0 + ry;
        float acc[8];
        #pragma unroll
        for (int ox = 0; ox < 8; ox++) acc[ox] = bv;

        #pragma unroll
        for (int ky = 0; ky < 7; ky++) {
            const int iy = yy + ky - 3;
            if (iy < 0 || iy >= H_) continue;
            float row[14];
            const float* rp = xz + (rowbase + (size_t)iy * W_) * (2 * E_) + e;
            #pragma unroll
            for (int c = 0; c < 14; c++) {
                const int ix = tx0 + c - 3;
                row[c] = (ix >= 0 && ix < W_) ? rp[(size_t)ix * (2 * E_)] : 0.f;
            }
            #pragma unroll
            for (int kx = 0; kx < 7; kx++) {
                const float wv = wsh[(ky * 7 + kx) * 128 + threadIdx.x];
                #pragma unroll
                for (int ox = 0; ox < 8; ox++)
                    acc[ox] = fmaf(row[ox + kx], wv, acc[ox]);
            }
        }

        float v[8];
        #pragma unroll
        for (int ox = 0; ox < 8; ox++) {
            const float sig = 1.f / (1.f + __expf(-acc[ox]));
            v[ox] = acc[ox] * sig;
            const size_t row = rowbase + yy * W_ + tx0 + ox;
            __nv_bfloat16 hi = __float2bfloat16(v[ox]);
            __nv_bfloat16 lo = __float2bfloat16(v[ox] - __bfloat162float(hi));
            const size_t ab = row * (3 * E_) + e;
            uaug[ab] = hi; uaug[ab + E_] = lo; uaug[ab + 2 * E_] = hi;
        }
        float4* up = reinterpret_cast<float4*>(utbase + yy * W_ + tx0);
        up[0] = make_float4(v[0], v[1], v[2], v[3]);
        up[1] = make_float4(v[4], v[5], v[6], v[7]);
    }
}

// ============ selective scan (transposed d/u, fused B|C load) =================
__global__ __launch_bounds__(128) void scan_kernel(
    const float* __restrict__ delta_t, const float* __restrict__ u_t,
    const float* __restrict__ xdbl,    const float* __restrict__ A_log,
    const float* __restrict__ Dp,      float* __restrict__ y)
{
    const int warp = (blockIdx.x * blockDim.x + threadIdx.x) >> 5;
    const int lane = threadIdx.x & 31;
    const int half = lane >> 4;
    const int n    = lane & 15;
    const int b    = warp / (E_ / 2);
    const int e    = (warp % (E_ / 2)) * 2 + half;

    const float a  = -__expf(A_log[e * N_ + n]);
    const float dp = Dp[e];
    float s = 0.f;

    const float* dptr = delta_t + ((size_t)b * E_ + e) * L_;
    const float* uptr = u_t     + ((size_t)b * E_ + e) * L_;
    const float* xrow = xdbl + (size_t)b * L_ * XD_ + R_ + lane;  // lane<16: B, >=16: C
    float*       yptr = y    + (size_t)b * L_ * E_ + e;

    for (int t = 0; t < L_; t += 4) {
        const float4 d4 = *reinterpret_cast<const float4*>(dptr + t);
        const float4 u4 = *reinterpret_cast<const float4*>(uptr + t);
        float bc[4];
        #pragma unroll
        for (int q = 0; q < 4; q++)
            bc[q] = __ldg(xrow + (size_t)(t + q) * XD_);

        const float d[4]  = {d4.x, d4.y, d4.z, d4.w};
        const float uv[4] = {u4.x, u4.y, u4.z, u4.w};
        float v[4];
        #pragma unroll
        for (int q = 0; q < 4; q++) {
            const float other = __shfl_xor_sync(0xffffffffu, bc[q], 16);
            const float Bn = half ? other : bc[q];
            const float Cn = half ? bc[q] : other;
            s = fmaf(s, __expf(d[q] * a), (d[q] * uv[q]) * Bn);
            v[q] = s * Cn;
        }
        #pragma unroll
        for (int q = 0; q < 4; q++) {
            v[q] += __shfl_xor_sync(0xffffffffu, v[q], 1);
            v[q] += __shfl_xor_sync(0xffffffffu, v[q], 2);
            v[q] += __shfl_xor_sync(0xffffffffu, v[q], 4);
            v[q] += __shfl_xor_sync(0xffffffffu, v[q], 8);
        }
        if (n == 0) {
            #pragma unroll
            for (int q = 0; q < 4; q++)
                yptr[(size_t)(t + q) * E_] = fmaf(uv[q], dp, v[q]);
        }
    }
}

// ============ batch-sum + gate -> g_aug =======================================
__global__ __launch_bounds__(256) void gate_kernel(
    const float* __restrict__ y, const float* __restrict__ xz,
    __nv_bfloat16* __restrict__ gaug)
{
    const int idx = blockIdx.x * blockDim.x + threadIdx.x;
    if (idx >= L_ * E_) return;
    float ssum = 0.f;
    #pragma unroll
    for (int b = 0; b < BATCH_; b++)
        ssum += y[((size_t)b * L_ * E_) + idx];
    const int t = idx / E_;
    const int e = idx - t * E_;
    #pragma unroll
    for (int b = 0; b < BATCH_; b++) {
        const float zv = xz[((size_t)(b * L_ + t)) * (2 * E_) + E_ + e];
        const float sig = 1.f / (1.f + __expf(-zv));
        const float v = ssum * zv * sig;
        __nv_bfloat16 hi = __float2bfloat16(v);
        __nv_bfloat16 lo = __float2bfloat16(v - __bfloat162float(hi));
        const size_t ab = ((size_t)(b * L_ + t)) * (3 * E_) + e;
        gaug[ab] = hi; gaug[ab + E_] = lo; gaug[ab + 2 * E_] = hi;
    }
}

// ============ launch ==========================================================
extern "C" void kernel_launch(void* const* d_in, const int* in_sizes, int n_in,
                              void* d_out, int out_size)
{
    int base = 3;
    if (in_sizes[1] == 2 * E_ * DM_) base = 1;

    const float* x      = (const float*)d_in[0];
    const float* W_in   = (const float*)d_in[base + 0];
    const float* conv_w = (const float*)d_in[base + 1];
    const float* conv_b = (const float*)d_in[base + 2];
    const float* W_x    = (const float*)d_in[base + 3];
    const float* W_dt   = (const float*)d_in[base + 4];
    const float* b_dt   = (const float*)d_in[base + 5];
    const float* A_log  = (const float*)d_in[base + 6];
    const float* Dp     = (const float*)d_in[base + 7];
    const float* W_out  = (const float*)d_in[base + 8];
    float* out = (float*)d_out;

    float *xz, *ut, *xdbl, *dlt, *y;
    __nv_bfloat16 *xaug, *uaug, *gaug, *wina, *wxa, *woa;
    cudaGetSymbolAddress((void**)&xz,    g_xz);
    cudaGetSymbolAddress((void**)&ut,    g_ut);
    cudaGetSymbolAddress((void**)&xdbl,  g_xdbl);
    cudaGetSymbolAddress((void**)&dlt,   g_dt);
    cudaGetSymbolAddress((void**)&y,     g_y);
    cudaGetSymbolAddress((void**)&xaug,  g_xaug);
    cudaGetSymbolAddress((void**)&uaug,  g_uaug);
    cudaGetSymbolAddress((void**)&gaug,  g_gaug);
    cudaGetSymbolAddress((void**)&wina,  g_wina);
    cudaGetSymbolAddress((void**)&wxa,   g_wxa);
    cudaGetSymbolAddress((void**)&woa,   g_woa);

    split_bf16<<<(ROWS_ * DM_ + 255) / 256, 256>>>(x, xaug, ROWS_, DM_, 0);
    split_bf16<<<(2 * E_ * DM_ + 255) / 256, 256>>>(W_in, wina, 2 * E_, DM_, 1);
    split_bf16<<<(XD_ * E_ + 255) / 256, 256>>>(W_x, wxa, XD_, E_, 1);
    split_bf16<<<(DM_ * E_ + 255) / 256, 256>>>(W_out, woa, DM_, E_, 1);

    // 1) xz = x @ W_in^T   (Kaug=576, N=768)
    wmma_gemm<4, false><<<dim3(6, ROWS_ / 128), 128>>>(xaug, wina, xz, 2 * E_, 3 * DM_, 2 * E_);
    // 2) conv + silu -> u_t, uaug
    dwconv_silu<<<dim3(3, 64, BATCH_), 128>>>(xz, conv_w, conv_b, ut, uaug);
    // 3) x_dbl = u @ W_x^T  (Kaug=1152, N=44, guarded)
    wmma_gemm<2, true><<<dim3(1, ROWS_ / 128), 128>>>(uaug, wxa, xdbl, XD_, 3 * E_, XD_);
    // 4) delta (transposed out)
    dt_kernel<<<ROWS_ / 32, 384>>>(xdbl, W_dt, b_dt, dlt);
    // 5) scan
    scan_kernel<<<(BATCH_ * (E_ / 2)) / 4, 128>>>(dlt, ut, xdbl, A_log, Dp, y);
    // 6) gate -> g_aug
    gate_kernel<<<(L_ * E_ + 255) / 256, 256>>>(y, xz, gaug);
    // 7) out = g @ W_out^T  (Kaug=1152, N=192; block 1 stores only valid frags)
    wmma_gemm<4, false><<<dim3(2, ROWS_ / 128), 128>>>(gaug, woa, out, DM_, 3 * E_, DM_);
}

// round 7
// speedup vs baseline: 1.9967x; 1.0229x over previous
#include <cuda_runtime.h>
#include <cuda_bf16.h>
#include <mma.h>
#include <cstdint>

using namespace nvcuda;

#define BATCH_ 8
#define H_ 64
#define W_ 64
#define L_ 4096
#define DM_ 192
#define E_ 384
#define N_ 16
#define R_ 12
#define XD_ 44
#define ROWS_ (BATCH_*L_)

// ---------------- cp.async helpers ------------------------------------------
__device__ __forceinline__ uint32_t smem_u32(const void* p) {
    uint32_t a;
    asm("{ .reg .u64 t; cvta.to.shared.u64 t, %1; cvt.u32.u64 %0, t; }" : "=r"(a) : "l"(p));
    return a;
}
#define CP_ASYNC16(dst, src, szbytes) \
    asm volatile("cp.async.cg.shared.global [%0], [%1], 16, %2;" \
                 :: "r"(dst), "l"(src), "r"(szbytes))
#define CP_COMMIT() asm volatile("cp.async.commit_group;")
#define CP_WAIT1()  asm volatile("cp.async.wait_group 1;")

// ---------------- scratch ----------------------------------------------------
__device__ float g_xz   [(size_t)ROWS_ * 2 * E_];
__device__ float g_ut   [(size_t)ROWS_ * E_];     // u transposed [b][e][t]
__device__ float g_xdbl [(size_t)ROWS_ * XD_];
__device__ float g_dt   [(size_t)ROWS_ * E_];     // delta transposed [b][e][t]
__device__ float g_y    [(size_t)ROWS_ * E_];     // [b][t][e]
__device__ __nv_bfloat16 g_xaug [(size_t)ROWS_ * 3 * DM_];
__device__ __nv_bfloat16 g_uaug [(size_t)ROWS_ * 3 * E_];
__device__ __nv_bfloat16 g_gaug [(size_t)ROWS_ * 3 * E_];
__device__ __nv_bfloat16 g_wina [(size_t)(2*E_) * 3 * DM_];
__device__ __nv_bfloat16 g_wxa  [(size_t)XD_ * 3 * E_];
__device__ __nv_bfloat16 g_woa  [(size_t)DM_ * 3 * E_];

// ---------- hi/lo split. variant 0 (activations): [hi|lo|hi]; 1 (weights): [hi|hi|lo]
__global__ void split_bf16(const float* __restrict__ src, __nv_bfloat16* __restrict__ dst,
                           int rows, int K, int variant)
{
    int idx = blockIdx.x * 256 + threadIdx.x;
    if (idx >= rows * K) return;
    int r = idx / K, k = idx - r * K;
    float v = src[idx];
    __nv_bfloat16 hi = __float2bfloat16(v);
    __nv_bfloat16 lo = __float2bfloat16(v - __bfloat162float(hi));
    size_t base = (size_t)r * 3 * K + k;
    if (variant == 0) { dst[base] = hi; dst[base + K] = lo; dst[base + 2 * K] = hi; }
    else              { dst[base] = hi; dst[base + K] = hi; dst[base + 2 * K] = lo; }
}

// ============ WMMA bf16 GEMM, 4 warps, warp tile 64 x (NFR*16) ================
// CTA tile 128 x (NFR*32). BK=32 double-buffered cp.async. 128 threads.
template<int NFR, bool GUARDN>
__global__ __launch_bounds__(128) void wmma_gemm(
    const __nv_bfloat16* __restrict__ Aaug,
    const __nv_bfloat16* __restrict__ Baug,
    float* __restrict__ C, int ldc, int Kaug, int Nout)
{
    constexpr int BM = 128, BK = 32;
    constexpr int BN = NFR * 32;
    constexpr int WNC = BN / 2;
    constexpr int LDS = BK + 16;                // 48 bf16 = 96B rows
    constexpr int ABYTES = 2 * BM * LDS * 2;
    constexpr int BBYTES = 2 * BN * LDS * 2;
    constexpr int AB = ABYTES + BBYTES;
    constexpr int SBYTES = (GUARDN && BM * BN * 4 > AB) ? BM * BN * 4 : AB;
    __shared__ __align__(32) char smem_raw[SBYTES];

    typedef __nv_bfloat16 ARow[BM][LDS];
    typedef __nv_bfloat16 BRow[BN][LDS];
    ARow* sA = reinterpret_cast<ARow*>(smem_raw);
    BRow* sB = reinterpret_cast<BRow*>(smem_raw + ABYTES);

    const int tid  = threadIdx.x;
    const int wid  = tid >> 5;
    const int wy   = wid & 1;
    const int wx   = wid >> 1;
    const int row0 = blockIdx.y * BM;
    const int col0 = blockIdx.x * BN;

    wmma::fragment<wmma::accumulator, 16, 16, 16, float> acc[4][NFR];
    #pragma unroll
    for (int i = 0; i < 4; i++)
        #pragma unroll
        for (int j = 0; j < NFR; j++) wmma::fill_fragment(acc[i][j], 0.f);

    const int nk = Kaug / BK;

    auto ld_tiles = [&](int kc, int buf) {
        #pragma unroll
        for (int it = 0; it < 4; it++) {              // A: 512 cp ops / 128 thr
            int idx = it * 128 + tid;
            int r = idx >> 2, ck = idx & 3;
            const __nv_bfloat16* src = Aaug + (size_t)(row0 + r) * Kaug + kc * BK + ck * 8;
            CP_ASYNC16(smem_u32(&sA[buf][r][ck * 8]), src, 16);
        }
        #pragma unroll
        for (int it = 0; it < NFR; it++) {            // B: BN*4 = NFR*128 ops
            int idx = it * 128 + tid;
            int r = idx >> 2, ck = idx & 3;
            int n = col0 + r;
            const __nv_bfloat16* src = Baug + (size_t)n * Kaug + kc * BK + ck * 8;
            CP_ASYNC16(smem_u32(&sB[buf][r][ck * 8]), src, (n < Nout) ? 16 : 0);
        }
    };

    ld_tiles(0, 0);
    CP_COMMIT();

    for (int kt = 0; kt < nk; kt++) {
        const int buf = kt & 1;
        if (kt + 1 < nk) ld_tiles(kt + 1, buf ^ 1);
        CP_COMMIT();
        CP_WAIT1();
        __syncthreads();

        #pragma unroll
        for (int ks = 0; ks < 2; ks++) {
            wmma::fragment<wmma::matrix_a, 16, 16, 16, __nv_bfloat16, wmma::row_major> af[4];
            wmma::fragment<wmma::matrix_b, 16, 16, 16, __nv_bfloat16, wmma::col_major> bf[NFR];
            #pragma unroll
            for (int i = 0; i < 4; i++)
                wmma::load_matrix_sync(af[i], &sA[buf][wy * 64 + i * 16][ks * 16], LDS);
            #pragma unroll
            for (int j = 0; j < NFR; j++)
                wmma::load_matrix_sync(bf[j], &sB[buf][wx * WNC + j * 16][ks * 16], LDS);
            #pragma unroll
            for (int i = 0; i < 4; i++)
                #pragma unroll
                for (int j = 0; j < NFR; j++)
                    wmma::mma_sync(acc[i][j], af[i], bf[j], acc[i][j]);
        }
        __syncthreads();
    }

    if (!GUARDN) {
        #pragma unroll
        for (int i = 0; i < 4; i++)
            #pragma unroll
            for (int j = 0; j < NFR; j++) {
                int cc = col0 + wx * WNC + j * 16;
                if (cc + 16 <= Nout)
                    wmma::store_matrix_sync(
                        C + (size_t)(row0 + wy * 64 + i * 16) * ldc + cc,
                        acc[i][j], ldc, wmma::mem_row_major);
            }
    } else {
        float* stage = reinterpret_cast<float*>(smem_raw);
        __syncthreads();
        #pragma unroll
        for (int i = 0; i < 4; i++)
            #pragma unroll
            for (int j = 0; j < NFR; j++)
                wmma::store_matrix_sync(
                    stage + (size_t)(wy * 64 + i * 16) * BN + wx * WNC + j * 16,
                    acc[i][j], BN, wmma::mem_row_major);
        __syncthreads();
        for (int idx = tid; idx < BM * BN; idx += 128) {
            int r = idx / BN, c = idx - r * BN;
            if (col0 + c < Nout)
                C[(size_t)(row0 + r) * ldc + col0 + c] = stage[idx];
        }
    }
}

// ============ delta = softplus(dt_r @ W_dt^T + 2*b_dt), transposed out ========
__global__ __launch_bounds__(384) void dt_kernel(
    const float* __restrict__ xdbl, const float* __restrict__ W_dt,
    const float* __restrict__ b_dt, float* __restrict__ delta_t)
{
    __shared__ float wsh[E_ * R_];
    __shared__ float dsh[32][R_];
    const int e = threadIdx.x;
    for (int i = e; i < E_ * R_; i += 384) wsh[i] = W_dt[i];
    const int row0 = blockIdx.x * 32;
    const int b  = row0 >> 12;
    const int t0 = row0 & (L_ - 1);
    {
        const int r = e / R_, k = e - r * R_;
        dsh[r][k] = xdbl[(size_t)(row0 + r) * XD_ + k];
    }
    __syncthreads();
    float w[R_];
    #pragma unroll
    for (int k = 0; k < R_; k++) w[k] = wsh[e * R_ + k];
    const float b2 = 2.f * b_dt[e];
    float out[32];
    #pragma unroll 4
    for (int r = 0; r < 32; r++) {
        float acc = b2;
        #pragma unroll
        for (int k = 0; k < R_; k++) acc = fmaf(dsh[r][k], w[k], acc);
        out[r] = (acc > 20.f) ? acc : log1pf(__expf(acc));
    }
    float4* dst = reinterpret_cast<float4*>(delta_t + ((size_t)b * E_ + e) * L_ + t0);
    #pragma unroll
    for (int q = 0; q < 8; q++)
        dst[q] = make_float4(out[4*q], out[4*q+1], out[4*q+2], out[4*q+3]);
}

// ============ depthwise 7x7 conv + SiLU; writes u_t [b][e][t] + uaug ==========
__global__ __launch_bounds__(128) void dwconv_silu(
    const float* __restrict__ xz, const float* __restrict__ cw,
    const float* __restrict__ cb, float* __restrict__ u_t,
    __nv_bfloat16* __restrict__ uaug)
{
    const int e   = blockIdx.x * 128 + threadIdx.x;
    const int ty0 = (blockIdx.y / (W_ / 8)) * 8;
    const int tx0 = (blockIdx.y % (W_ / 8)) * 8;
    const int b   = blockIdx.z;

    __shared__ float wsh[49 * 128];
    #pragma unroll 1
    for (int j = 0; j < 49; j++)
        wsh[j * 128 + threadIdx.x] = cw[(size_t)e * 49 + j];
    __syncthreads();

    const float bv = cb[e];
    const size_t rowbase = (size_t)b * L_;
    float* utbase = u_t + ((size_t)b * E_ + e) * L_;

    #pragma unroll 1
    for (int ry = 0; ry < 8; ry++) {
        const int yy = ty0 + ry;
        float acc[8];
        #pragma unroll
        for (int ox = 0; ox < 8; ox++) acc[ox] = bv;

        #pragma unroll
        for (int ky = 0; ky < 7; ky++) {
            const int iy = yy + ky - 3;
            if (iy < 0 || iy >= H_) continue;
            float row[14];
            const float* rp = xz + (rowbase + (size_t)iy * W_) * (2 * E_) + e;
            #pragma unroll
            for (int c = 0; c < 14; c++) {
                const int ix = tx0 + c - 3;
                row[c] = (ix >= 0 && ix < W_) ? rp[(size_t)ix * (2 * E_)] : 0.f;
            }
            #pragma unroll
            for (int kx = 0; kx < 7; kx++) {
                const float wv = wsh[(ky * 7 + kx) * 128 + threadIdx.x];
                #pragma unroll
                for (int ox = 0; ox < 8; ox++)
                    acc[ox] = fmaf(row[ox + kx], wv, acc[ox]);
            }
        }

        float v[8];
        #pragma unroll
        for (int ox = 0; ox < 8; ox++) {
            const float sig = 1.f / (1.f + __expf(-acc[ox]));
            v[ox] = acc[ox] * sig;
            const size_t row = rowbase + yy * W_ + tx0 + ox;
            __nv_bfloat16 hi = __float2bfloat16(v[ox]);
            __nv_bfloat16 lo = __float2bfloat16(v[ox] - __bfloat162float(hi));
            const size_t ab = row * (3 * E_) + e;
            uaug[ab] = hi; uaug[ab + E_] = lo; uaug[ab + 2 * E_] = hi;
        }
        float4* up = reinterpret_cast<float4*>(utbase + yy * W_ + tx0);
        up[0] = make_float4(v[0], v[1], v[2], v[3]);
        up[1] = make_float4(v[4], v[5], v[6], v[7]);
    }
}

// ============ selective scan (transposed d/u, fused B|C load) =================
__global__ __launch_bounds__(128) void scan_kernel(
    const float* __restrict__ delta_t, const float* __restrict__ u_t,
    const float* __restrict__ xdbl,    const float* __restrict__ A_log,
    const float* __restrict__ Dp,      float* __restrict__ y)
{
    const int warp = (blockIdx.x * blockDim.x + threadIdx.x) >> 5;
    const int lane = threadIdx.x & 31;
    const int half = lane >> 4;
    const int n    = lane & 15;
    const int b    = warp / (E_ / 2);
    const int e    = (warp % (E_ / 2)) * 2 + half;

    const float a  = -__expf(A_log[e * N_ + n]);
    const float dp = Dp[e];
    float s = 0.f;

    const float* dptr = delta_t + ((size_t)b * E_ + e) * L_;
    const float* uptr = u_t     + ((size_t)b * E_ + e) * L_;
    const float* xrow = xdbl + (size_t)b * L_ * XD_ + R_ + lane;  // lane<16: B, >=16: C
    float*       yptr = y    + (size_t)b * L_ * E_ + e;

    for (int t = 0; t < L_; t += 4) {
        const float4 d4 = *reinterpret_cast<const float4*>(dptr + t);
        const float4 u4 = *reinterpret_cast<const float4*>(uptr + t);
        float bc[4];
        #pragma unroll
        for (int q = 0; q < 4; q++)
            bc[q] = __ldg(xrow + (size_t)(t + q) * XD_);

        const float d[4]  = {d4.x, d4.y, d4.z, d4.w};
        const float uv[4] = {u4.x, u4.y, u4.z, u4.w};
        float v[4];
        #pragma unroll
        for (int q = 0; q < 4; q++) {
            const float other = __shfl_xor_sync(0xffffffffu, bc[q], 16);
            const float Bn = half ? other : bc[q];
            const float Cn = half ? bc[q] : other;
            s = fmaf(s, __expf(d[q] * a), (d[q] * uv[q]) * Bn);
            v[q] = s * Cn;
        }
        #pragma unroll
        for (int q = 0; q < 4; q++) {
            v[q] += __shfl_xor_sync(0xffffffffu, v[q], 1);
            v[q] += __shfl_xor_sync(0xffffffffu, v[q], 2);
            v[q] += __shfl_xor_sync(0xffffffffu, v[q], 4);
            v[q] += __shfl_xor_sync(0xffffffffu, v[q], 8);
        }
        if (n == 0) {
            #pragma unroll
            for (int q = 0; q < 4; q++)
                yptr[(size_t)(t + q) * E_] = fmaf(uv[q], dp, v[q]);
        }
    }
}

// ============ batch-sum + gate -> g_aug =======================================
__global__ __launch_bounds__(256) void gate_kernel(
    const float* __restrict__ y, const float* __restrict__ xz,
    __nv_bfloat16* __restrict__ gaug)
{
    const int idx = blockIdx.x * blockDim.x + threadIdx.x;
    if (idx >= L_ * E_) return;
    float ssum = 0.f;
    #pragma unroll
    for (int b = 0; b < BATCH_; b++)
        ssum += y[((size_t)b * L_ * E_) + idx];
    const int t = idx / E_;
    const int e = idx - t * E_;
    #pragma unroll
    for (int b = 0; b < BATCH_; b++) {
        const float zv = xz[((size_t)(b * L_ + t)) * (2 * E_) + E_ + e];
        const float sig = 1.f / (1.f + __expf(-zv));
        const float v = ssum * zv * sig;
        __nv_bfloat16 hi = __float2bfloat16(v);
        __nv_bfloat16 lo = __float2bfloat16(v - __bfloat162float(hi));
        const size_t ab = ((size_t)(b * L_ + t)) * (3 * E_) + e;
        gaug[ab] = hi; gaug[ab + E_] = lo; gaug[ab + 2 * E_] = hi;
    }
}

// ============ launch ==========================================================
extern "C" void kernel_launch(void* const* d_in, const int* in_sizes, int n_in,
                              void* d_out, int out_size)
{
    int base = 3;
    if (in_sizes[1] == 2 * E_ * DM_) base = 1;

    const float* x      = (const float*)d_in[0];
    const float* W_in   = (const float*)d_in[base + 0];
    const float* conv_w = (const float*)d_in[base + 1];
    const float* conv_b = (const float*)d_in[base + 2];
    const float* W_x    = (const float*)d_in[base + 3];
    const float* W_dt   = (const float*)d_in[base + 4];
    const float* b_dt   = (const float*)d_in[base + 5];
    const float* A_log  = (const float*)d_in[base + 6];
    const float* Dp     = (const float*)d_in[base + 7];
    const float* W_out  = (const float*)d_in[base + 8];
    float* out = (float*)d_out;

    float *xz, *ut, *xdbl, *dlt, *y;
    __nv_bfloat16 *xaug, *uaug, *gaug, *wina, *wxa, *woa;
    cudaGetSymbolAddress((void**)&xz,    g_xz);
    cudaGetSymbolAddress((void**)&ut,    g_ut);
    cudaGetSymbolAddress((void**)&xdbl,  g_xdbl);
    cudaGetSymbolAddress((void**)&dlt,   g_dt);
    cudaGetSymbolAddress((void**)&y,     g_y);
    cudaGetSymbolAddress((void**)&xaug,  g_xaug);
    cudaGetSymbolAddress((void**)&uaug,  g_uaug);
    cudaGetSymbolAddress((void**)&gaug,  g_gaug);
    cudaGetSymbolAddress((void**)&wina,  g_wina);
    cudaGetSymbolAddress((void**)&wxa,   g_wxa);
    cudaGetSymbolAddress((void**)&woa,   g_woa);

    // launch order arranged so profiled launch (index 3) is GEMM1
    split_bf16<<<(ROWS_ * DM_ + 255) / 256, 256>>>(x, xaug, ROWS_, DM_, 0);        // 0
    split_bf16<<<(2 * E_ * DM_ + 255) / 256, 256>>>(W_in, wina, 2 * E_, DM_, 1);   // 1
    split_bf16<<<(XD_ * E_ + 255) / 256, 256>>>(W_x, wxa, XD_, E_, 1);             // 2
    // 1) xz = x @ W_in^T   (Kaug=576, N=768)                                      // 3
    wmma_gemm<4, false><<<dim3(6, ROWS_ / 128), 128>>>(xaug, wina, xz, 2 * E_, 3 * DM_, 2 * E_);
    // 2) conv + silu -> u_t, uaug                                                 // 4
    dwconv_silu<<<dim3(3, 64, BATCH_), 128>>>(xz, conv_w, conv_b, ut, uaug);
    split_bf16<<<(DM_ * E_ + 255) / 256, 256>>>(W_out, woa, DM_, E_, 1);           // 5
    // 3) x_dbl = u @ W_x^T  (Kaug=1152, N=44, guarded)                            // 6
    wmma_gemm<2, true><<<dim3(1, ROWS_ / 128), 128>>>(uaug, wxa, xdbl, XD_, 3 * E_, XD_);
    // 4) delta (transposed out)
    dt_kernel<<<ROWS_ / 32, 384>>>(xdbl, W_dt, b_dt, dlt);
    // 5) scan
    scan_kernel<<<(BATCH_ * (E_ / 2)) / 4, 128>>>(dlt, ut, xdbl, A_log, Dp, y);
    // 6) gate -> g_aug
    gate_kernel<<<(L_ * E_ + 255) / 256, 256>>>(y, xz, gaug);
    // 7) out = g @ W_out^T  (Kaug=1152, N=192 exact with BN=96)
    wmma_gemm<3, false><<<dim3(2, ROWS_ / 128), 128>>>(gaug, woa, out, DM_, 3 * E_, DM_);
}